// round 7
// baseline (speedup 1.0000x reference)
#include <cuda_runtime.h>
#include <cuda_bf16.h>

#define N_NODES 50000
#define E_EDGES 600000
#define FDIM    128
#define HDIM    16

// scratch (allocation-free rule: __device__ globals).
// NOTE: these symbols are ONLY referenced inside device code — passing them as
// kernel arguments from host code silently binds the host shadow copy (ATS on
// GB300 makes that dereferenceable, hence five rounds of silent zeros).
__device__ int   g_mode;               // 0=int32, 1=int64, 2=float32-encoded indices
__device__ float g_deg [N_NODES];
__device__ float g_dinv[N_NODES];
__device__ float g_h   [N_NODES * HDIM];   // h1 = x@W1, then z1 = relu(agg1+b1)
__device__ float g_acc1[N_NODES * HDIM];
__device__ float g_acc2[N_NODES * HDIM];

// Decode edge index element `pos` (pos = half*E_EDGES + e) under detected mode.
__device__ __forceinline__ int load_edge_idx(const unsigned int* __restrict__ ei,
                                             int mode, int pos) {
    if (mode == 1) return (int)ei[2 * pos];          // int64: low word
    unsigned int v = ei[pos];
    if (mode == 2) return (int)__int_as_float((int)v);  // float32-encoded
    return (int)v;                                      // int32
}

// ---------------- detect dtype encoding of edge_index ----------------
__global__ void detect_kernel(const unsigned int* __restrict__ w) {
    __shared__ int s_big, s_oddnz;
    if (threadIdx.x == 0) { s_big = 0; s_oddnz = 0; }
    __syncthreads();
    int big = 0, oddnz = 0;
    for (int i = threadIdx.x; i < 4096; i += blockDim.x) {
        unsigned int v = w[i];
        if (v >= 0x30000000u) big++;
        if ((i & 1) && v != 0u) oddnz++;
    }
    if (big)   atomicAdd(&s_big, big);
    if (oddnz) atomicAdd(&s_oddnz, oddnz);
    __syncthreads();
    if (threadIdx.x == 0) {
        if (s_big > 1024)      g_mode = 2;
        else if (s_oddnz == 0) g_mode = 1;
        else                   g_mode = 0;
    }
}

// ---------------- init: zero accumulators, deg=1 (self-loop) ----------------
__global__ void init_kernel() {
    int i = blockIdx.x * blockDim.x + threadIdx.x;
    if (i < N_NODES * HDIM) {
        g_acc1[i] = 0.0f;
        g_acc2[i] = 0.0f;
        if (i < N_NODES) g_deg[i] = 1.0f;
    }
}

// ---------------- degree count over targets ----------------
__global__ void deg_kernel(const unsigned int* __restrict__ ei) {
    int e = blockIdx.x * blockDim.x + threadIdx.x;
    if (e < E_EDGES) {
        int c = load_edge_idx(ei, g_mode, E_EDGES + e);
        if (c >= 0 && c < N_NODES)
            atomicAdd(&g_deg[c], 1.0f);
    }
}

__global__ void dinv_kernel() {
    int i = blockIdx.x * blockDim.x + threadIdx.x;
    if (i < N_NODES) g_dinv[i] = rsqrtf(g_deg[i]);
}

// ---------------- h = x @ W1  (50000x128 @ 128x16) ----------------
__global__ void gemm1_kernel(const float* __restrict__ x, const float* __restrict__ W1) {
    __shared__ float sW1[FDIM * HDIM];
    for (int i = threadIdx.x; i < FDIM * HDIM; i += blockDim.x)
        sW1[i] = W1[i];
    __syncthreads();

    int idx = blockIdx.x * blockDim.x + threadIdx.x;
    if (idx >= N_NODES * HDIM) return;
    int row = idx >> 4;
    int j   = idx & 15;

    const float4* xr = (const float4*)(x + (size_t)row * FDIM);
    float acc = 0.0f;
#pragma unroll
    for (int k4 = 0; k4 < FDIM / 4; k4++) {
        float4 xv = xr[k4];
        acc += xv.x * sW1[(k4 * 4 + 0) * HDIM + j];
        acc += xv.y * sW1[(k4 * 4 + 1) * HDIM + j];
        acc += xv.z * sW1[(k4 * 4 + 2) * HDIM + j];
        acc += xv.w * sW1[(k4 * 4 + 3) * HDIM + j];
    }
    g_h[idx] = acc;
}

// ---------------- aggregation: acc[c] += h[r]*dinv[r]*dinv[c] (+ self loops) ----
// PASS selects the destination accumulator INSIDE device code (device symbols
// must never be passed as kernel arguments from the host).
template <int PASS>
__global__ void agg_kernel(const unsigned int* __restrict__ ei) {
    int e = blockIdx.x * blockDim.x + threadIdx.x;
    if (e >= E_EDGES + N_NODES) return;

    const float* __restrict__ h  = g_h;
    float* __restrict__       acc = (PASS == 0) ? g_acc1 : g_acc2;

    int r, c;
    float norm;
    if (e < E_EDGES) {
        int mode = g_mode;
        r = load_edge_idx(ei, mode, e);
        c = load_edge_idx(ei, mode, E_EDGES + e);
        if (r < 0 || r >= N_NODES || c < 0 || c >= N_NODES) return;
        norm = g_dinv[r] * g_dinv[c];
    } else {
        r = c = e - E_EDGES;
        float d = g_dinv[r];
        norm = d * d;
    }

    const float4* hr = (const float4*)(h + r * HDIM);
    float*        ac = acc + c * HDIM;
#pragma unroll
    for (int p = 0; p < HDIM / 4; p++) {
        float4 v = hr[p];
        atomicAdd(ac + p * 4 + 0, v.x * norm);
        atomicAdd(ac + p * 4 + 1, v.y * norm);
        atomicAdd(ac + p * 4 + 2, v.z * norm);
        atomicAdd(ac + p * 4 + 3, v.w * norm);
    }
}

// ---------------- z1 = relu(acc1 + b1), written back to g_h ----------------
__global__ void relu_bias_kernel(const float* __restrict__ b1) {
    int idx = blockIdx.x * blockDim.x + threadIdx.x;
    if (idx >= N_NODES * HDIM) return;
    int j = idx & 15;
    g_h[idx] = fmaxf(g_acc1[idx] + b1[j], 0.0f);
}

// ---------------- out = log_softmax(acc2 @ W2 + b2) --- warp per row --------
__global__ void final_kernel(const float* __restrict__ W2, const float* __restrict__ b2,
                             float* __restrict__ out) {
    __shared__ float sW2[HDIM * FDIM];
    __shared__ float sb2[FDIM];
    for (int i = threadIdx.x; i < HDIM * FDIM; i += blockDim.x) sW2[i] = W2[i];
    for (int i = threadIdx.x; i < FDIM; i += blockDim.x)        sb2[i] = b2[i];
    __syncthreads();

    int warp = (blockIdx.x * blockDim.x + threadIdx.x) >> 5;
    int lane = threadIdx.x & 31;
    if (warp >= N_NODES) return;

    const float* ar = g_acc2 + warp * HDIM;
    float a[HDIM];
#pragma unroll
    for (int k = 0; k < HDIM; k++) a[k] = ar[k];   // broadcast loads

    int c0 = lane * 4;
    float o0 = sb2[c0 + 0], o1 = sb2[c0 + 1], o2 = sb2[c0 + 2], o3 = sb2[c0 + 3];
#pragma unroll
    for (int k = 0; k < HDIM; k++) {
        float4 w = *(const float4*)&sW2[k * FDIM + c0];
        o0 += a[k] * w.x; o1 += a[k] * w.y; o2 += a[k] * w.z; o3 += a[k] * w.w;
    }

    float m = fmaxf(fmaxf(o0, o1), fmaxf(o2, o3));
#pragma unroll
    for (int off = 16; off > 0; off >>= 1)
        m = fmaxf(m, __shfl_xor_sync(0xFFFFFFFFu, m, off));

    float s = expf(o0 - m) + expf(o1 - m) + expf(o2 - m) + expf(o3 - m);
#pragma unroll
    for (int off = 16; off > 0; off >>= 1)
        s += __shfl_xor_sync(0xFFFFFFFFu, s, off);
    float lse = m + logf(s);

    float4 r = make_float4(o0 - lse, o1 - lse, o2 - lse, o3 - lse);
    *(float4*)(out + (size_t)warp * FDIM + c0) = r;
}

extern "C" void kernel_launch(void* const* d_in, const int* in_sizes, int n_in,
                              void* d_out, int out_size) {
    // identify inputs by size (elements OR bytes — all candidates disjoint)
    const float*        x  = nullptr;
    const unsigned int* ei = nullptr;
    const float*        W1 = nullptr;
    const float*        W2 = nullptr;
    const float*        b1 = nullptr;
    const float*        b2 = nullptr;

    for (int i = 0; i < n_in; i++) {
        long long sz = in_sizes[i];
        if (sz == 6400000LL || sz == 25600000LL)        x  = (const float*)d_in[i];
        else if (sz == 1200000LL || sz == 2400000LL ||
                 sz == 4800000LL || sz == 9600000LL)     ei = (const unsigned int*)d_in[i];
        else if (sz == 2048LL || sz == 8192LL) { if (!W1) W1 = (const float*)d_in[i];
                                                 else     W2 = (const float*)d_in[i]; }
        else if (sz == 16LL  || sz == 64LL)              b1 = (const float*)d_in[i];
        else if (sz == 128LL || sz == 512LL)             b2 = (const float*)d_in[i];
    }
    if (!x)  x  = (const float*)d_in[0];
    if (!ei) ei = (const unsigned int*)d_in[1];
    if (!W1) W1 = (const float*)d_in[2];
    if (!b1) b1 = (const float*)d_in[3];
    if (!W2) W2 = (const float*)d_in[4];
    if (!b2) b2 = (const float*)d_in[5];

    float* out = (float*)d_out;
    const int T = 256;

    detect_kernel<<<1, 256>>>(ei);
    init_kernel<<<(N_NODES * HDIM + T - 1) / T, T>>>();
    deg_kernel<<<(E_EDGES + T - 1) / T, T>>>(ei);
    dinv_kernel<<<(N_NODES + T - 1) / T, T>>>();
    gemm1_kernel<<<(N_NODES * HDIM + T - 1) / T, T>>>(x, W1);
    agg_kernel<0><<<(E_EDGES + N_NODES + T - 1) / T, T>>>(ei);
    relu_bias_kernel<<<(N_NODES * HDIM + T - 1) / T, T>>>(b1);
    agg_kernel<1><<<(E_EDGES + N_NODES + T - 1) / T, T>>>(ei);
    final_kernel<<<(N_NODES * 32 + T - 1) / T, T>>>(W2, b2, out);
}

// round 8
// speedup vs baseline: 1.6755x; 1.6755x over previous
#include <cuda_runtime.h>
#include <cuda_bf16.h>

#define N_NODES 50000
#define E_EDGES 600000
#define FDIM    128
#define HDIM    16

#define INIT_BLOCKS ((N_NODES * HDIM + 255) / 256)   // 3125
#define GEMM_BLOCKS ((N_NODES * HDIM + 255) / 256)   // 3125
#define DINV_BLOCKS ((N_NODES + 255) / 256)          // 196

// scratch — device symbols referenced ONLY inside device code
__device__ int   g_mode;
__device__ float g_deg [N_NODES];
__device__ float g_dinv[N_NODES];
__device__ float g_h   [N_NODES * HDIM];
__device__ float g_acc1[N_NODES * HDIM];
__device__ float g_acc2[N_NODES * HDIM];

__device__ __forceinline__ int load_edge_idx(const unsigned int* __restrict__ ei,
                                             int mode, int pos) {
    if (mode == 1) return (int)ei[2 * pos];             // int64: low word
    unsigned int v = ei[pos];
    if (mode == 2) return (int)__int_as_float((int)v);  // float32-encoded
    return (int)v;                                      // int32
}

__device__ __forceinline__ void red_add_f4(float* addr, float4 v) {
    asm volatile("red.global.add.v4.f32 [%0], {%1,%2,%3,%4};"
                 :: "l"(addr), "f"(v.x), "f"(v.y), "f"(v.z), "f"(v.w) : "memory");
}

// ---- launch 0: init accumulators + deg, block 0 also detects edge dtype ----
__global__ void init_detect_kernel(const unsigned int* __restrict__ w) {
    int i = blockIdx.x * blockDim.x + threadIdx.x;
    if (i < N_NODES * HDIM) {
        g_acc1[i] = 0.0f;
        g_acc2[i] = 0.0f;
        if (i < N_NODES) g_deg[i] = 1.0f;   // self-loop
    }
    if (blockIdx.x == 0) {
        __shared__ int s_big, s_oddnz;
        if (threadIdx.x == 0) { s_big = 0; s_oddnz = 0; }
        __syncthreads();
        int big = 0, oddnz = 0;
        for (int k = threadIdx.x; k < 4096; k += blockDim.x) {
            unsigned int v = w[k];
            if (v >= 0x30000000u) big++;
            if ((k & 1) && v != 0u) oddnz++;
        }
        if (big)   atomicAdd(&s_big, big);
        if (oddnz) atomicAdd(&s_oddnz, oddnz);
        __syncthreads();
        if (threadIdx.x == 0) {
            if (s_big > 1024)      g_mode = 2;
            else if (s_oddnz == 0) g_mode = 1;
            else                   g_mode = 0;
        }
    }
}

// ---- launch 1: degree count over targets ----
__global__ void deg_kernel(const unsigned int* __restrict__ ei) {
    int e = blockIdx.x * blockDim.x + threadIdx.x;
    if (e < E_EDGES) {
        int c = load_edge_idx(ei, g_mode, E_EDGES + e);
        if (c >= 0 && c < N_NODES)
            atomicAdd(&g_deg[c], 1.0f);
    }
}

// ---- launch 2: fused  [blocks 0..GEMM) gemm1 | blocks GEMM.. dinv] ----
__global__ void gemm_dinv_kernel(const float* __restrict__ x, const float* __restrict__ W1) {
    if (blockIdx.x >= GEMM_BLOCKS) {
        int i = (blockIdx.x - GEMM_BLOCKS) * blockDim.x + threadIdx.x;
        if (i < N_NODES) g_dinv[i] = rsqrtf(g_deg[i]);
        return;
    }
    __shared__ float sW1[FDIM * HDIM];
    for (int i = threadIdx.x; i < FDIM * HDIM; i += blockDim.x)
        sW1[i] = W1[i];
    __syncthreads();

    int idx = blockIdx.x * blockDim.x + threadIdx.x;
    if (idx >= N_NODES * HDIM) return;
    int row = idx >> 4;
    int j   = idx & 15;

    const float4* xr = (const float4*)(x + (size_t)row * FDIM);
    float acc = 0.0f;
#pragma unroll
    for (int k4 = 0; k4 < FDIM / 4; k4++) {
        float4 xv = xr[k4];
        acc += xv.x * sW1[(k4 * 4 + 0) * HDIM + j];
        acc += xv.y * sW1[(k4 * 4 + 1) * HDIM + j];
        acc += xv.z * sW1[(k4 * 4 + 2) * HDIM + j];
        acc += xv.w * sW1[(k4 * 4 + 3) * HDIM + j];
    }
    g_h[idx] = acc;
}

// ---- launches 3 & 5: aggregation with vector RED ----
template <int PASS>
__global__ void agg_kernel(const unsigned int* __restrict__ ei) {
    int e = blockIdx.x * blockDim.x + threadIdx.x;
    if (e >= E_EDGES + N_NODES) return;

    const float* __restrict__ h   = g_h;
    float* __restrict__       acc = (PASS == 0) ? g_acc1 : g_acc2;

    int r, c;
    float norm;
    if (e < E_EDGES) {
        int mode = g_mode;
        r = load_edge_idx(ei, mode, e);
        c = load_edge_idx(ei, mode, E_EDGES + e);
        if (r < 0 || r >= N_NODES || c < 0 || c >= N_NODES) return;
        norm = g_dinv[r] * g_dinv[c];
    } else {
        r = c = e - E_EDGES;
        float d = g_dinv[r];
        norm = d * d;
    }

    const float4* hr = (const float4*)(h + r * HDIM);
    float*        ac = acc + c * HDIM;
#pragma unroll
    for (int p = 0; p < HDIM / 4; p++) {
        float4 v = hr[p];
        v.x *= norm; v.y *= norm; v.z *= norm; v.w *= norm;
        red_add_f4(ac + p * 4, v);
    }
}

// ---- launch 4: z1 = relu(acc1 + b1) -> g_h ----
__global__ void relu_bias_kernel(const float* __restrict__ b1) {
    int idx = blockIdx.x * blockDim.x + threadIdx.x;
    if (idx >= N_NODES * HDIM) return;
    int j = idx & 15;
    g_h[idx] = fmaxf(g_acc1[idx] + b1[j], 0.0f);
}

// ---- launch 6: out = log_softmax(acc2 @ W2 + b2) --- warp per row ----
__global__ void final_kernel(const float* __restrict__ W2, const float* __restrict__ b2,
                             float* __restrict__ out) {
    __shared__ float sW2[HDIM * FDIM];
    __shared__ float sb2[FDIM];
    for (int i = threadIdx.x; i < HDIM * FDIM; i += blockDim.x) sW2[i] = W2[i];
    for (int i = threadIdx.x; i < FDIM; i += blockDim.x)        sb2[i] = b2[i];
    __syncthreads();

    int warp = (blockIdx.x * blockDim.x + threadIdx.x) >> 5;
    int lane = threadIdx.x & 31;
    if (warp >= N_NODES) return;

    const float* ar = g_acc2 + warp * HDIM;
    float a[HDIM];
#pragma unroll
    for (int k = 0; k < HDIM; k++) a[k] = ar[k];

    int c0 = lane * 4;
    float o0 = sb2[c0 + 0], o1 = sb2[c0 + 1], o2 = sb2[c0 + 2], o3 = sb2[c0 + 3];
#pragma unroll
    for (int k = 0; k < HDIM; k++) {
        float4 w = *(const float4*)&sW2[k * FDIM + c0];
        o0 += a[k] * w.x; o1 += a[k] * w.y; o2 += a[k] * w.z; o3 += a[k] * w.w;
    }

    float m = fmaxf(fmaxf(o0, o1), fmaxf(o2, o3));
#pragma unroll
    for (int off = 16; off > 0; off >>= 1)
        m = fmaxf(m, __shfl_xor_sync(0xFFFFFFFFu, m, off));

    float s = expf(o0 - m) + expf(o1 - m) + expf(o2 - m) + expf(o3 - m);
#pragma unroll
    for (int off = 16; off > 0; off >>= 1)
        s += __shfl_xor_sync(0xFFFFFFFFu, s, off);
    float lse = m + logf(s);

    float4 r = make_float4(o0 - lse, o1 - lse, o2 - lse, o3 - lse);
    *(float4*)(out + (size_t)warp * FDIM + c0) = r;
}

extern "C" void kernel_launch(void* const* d_in, const int* in_sizes, int n_in,
                              void* d_out, int out_size) {
    // identify inputs by size (elements OR bytes — all candidates disjoint)
    const float*        x  = nullptr;
    const unsigned int* ei = nullptr;
    const float*        W1 = nullptr;
    const float*        W2 = nullptr;
    const float*        b1 = nullptr;
    const float*        b2 = nullptr;

    for (int i = 0; i < n_in; i++) {
        long long sz = in_sizes[i];
        if (sz == 6400000LL || sz == 25600000LL)        x  = (const float*)d_in[i];
        else if (sz == 1200000LL || sz == 2400000LL ||
                 sz == 4800000LL || sz == 9600000LL)     ei = (const unsigned int*)d_in[i];
        else if (sz == 2048LL || sz == 8192LL) { if (!W1) W1 = (const float*)d_in[i];
                                                 else     W2 = (const float*)d_in[i]; }
        else if (sz == 16LL  || sz == 64LL)              b1 = (const float*)d_in[i];
        else if (sz == 128LL || sz == 512LL)             b2 = (const float*)d_in[i];
    }
    if (!x)  x  = (const float*)d_in[0];
    if (!ei) ei = (const unsigned int*)d_in[1];
    if (!W1) W1 = (const float*)d_in[2];
    if (!b1) b1 = (const float*)d_in[3];
    if (!W2) W2 = (const float*)d_in[4];
    if (!b2) b2 = (const float*)d_in[5];

    float* out = (float*)d_out;
    const int T = 256;

    init_detect_kernel<<<INIT_BLOCKS, T>>>(ei);                            // 0
    deg_kernel<<<(E_EDGES + T - 1) / T, T>>>(ei);                          // 1
    gemm_dinv_kernel<<<GEMM_BLOCKS + DINV_BLOCKS, T>>>(x, W1);             // 2
    agg_kernel<0><<<(E_EDGES + N_NODES + T - 1) / T, T>>>(ei);             // 3
    relu_bias_kernel<<<(N_NODES * HDIM + T - 1) / T, T>>>(b1);             // 4
    agg_kernel<1><<<(E_EDGES + N_NODES + T - 1) / T, T>>>(ei);             // 5  <- ncu -s 5 captures this
    final_kernel<<<(N_NODES * 32 + T - 1) / T, T>>>(W2, b2, out);          // 6
}

// round 9
// speedup vs baseline: 1.7804x; 1.0626x over previous
#include <cuda_runtime.h>
#include <cuda_bf16.h>

#define N_NODES 50000
#define E_EDGES 600000
#define FDIM    128
#define HDIM    16

// scratch — device symbols referenced ONLY inside device code.
// Self-cleaning invariant: every kernel that consumes mutable state resets it,
// so each graph replay starts from the same (zero) state.
__device__ int   g_mode;
__device__ float g_deg [N_NODES];            // 0 at rest; deg counts land here
__device__ float g_dinv[N_NODES];
__device__ float g_h   [N_NODES * HDIM];     // h1s = dinv*(x@W1), then z1s = dinv*z1
__device__ float g_acc1[N_NODES * HDIM];     // 0 at rest
__device__ float g_acc2[N_NODES * HDIM];     // 0 at rest

__device__ __forceinline__ int load_edge_idx(const unsigned int* __restrict__ ei,
                                             int mode, int pos) {
    if (mode == 1) return (int)ei[2 * pos];             // int64: low word
    unsigned int v = ei[pos];
    if (mode == 2) return (int)__int_as_float((int)v);  // float32-encoded
    return (int)v;                                      // int32
}

__device__ __forceinline__ void red_add_f4(float* addr, float4 v) {
    asm volatile("red.global.add.v4.f32 [%0], {%1,%2,%3,%4};"
                 :: "l"(addr), "f"(v.x), "f"(v.y), "f"(v.z), "f"(v.w) : "memory");
}

// ---- launch 0: detect edge dtype (1 block) ----
__global__ void detect_kernel(const unsigned int* __restrict__ w) {
    __shared__ int s_big, s_oddnz;
    if (threadIdx.x == 0) { s_big = 0; s_oddnz = 0; }
    __syncthreads();
    int big = 0, oddnz = 0;
    for (int k = threadIdx.x; k < 4096; k += blockDim.x) {
        unsigned int v = w[k];
        if (v >= 0x30000000u) big++;
        if ((k & 1) && v != 0u) oddnz++;
    }
    if (big)   atomicAdd(&s_big, big);
    if (oddnz) atomicAdd(&s_oddnz, oddnz);
    __syncthreads();
    if (threadIdx.x == 0) {
        if (s_big > 1024)      g_mode = 2;
        else if (s_oddnz == 0) g_mode = 1;
        else                   g_mode = 0;
    }
}

// ---- launch 1: degree count over targets (g_deg starts at 0) ----
__global__ void deg_kernel(const unsigned int* __restrict__ ei) {
    int e = blockIdx.x * blockDim.x + threadIdx.x;
    if (e < E_EDGES) {
        int c = load_edge_idx(ei, g_mode, E_EDGES + e);
        if (c >= 0 && c < N_NODES)
            atomicAdd(&g_deg[c], 1.0f);
    }
}

// ---- launch 2: h1s = dinv * (x @ W1); also publish g_dinv and reset g_deg ----
__global__ void gemm1_kernel(const float* __restrict__ x, const float* __restrict__ W1) {
    __shared__ float sW1[FDIM * HDIM];
    for (int i = threadIdx.x; i < FDIM * HDIM; i += blockDim.x)
        sW1[i] = W1[i];
    __syncthreads();

    int idx = blockIdx.x * blockDim.x + threadIdx.x;
    if (idx >= N_NODES * HDIM) return;
    int row = idx >> 4;
    int j   = idx & 15;

    float dinv = rsqrtf(g_deg[row] + 1.0f);   // +1 = self-loop

    const float4* xr = (const float4*)(x + (size_t)row * FDIM);
    float acc = 0.0f;
#pragma unroll
    for (int k4 = 0; k4 < FDIM / 4; k4++) {
        float4 xv = xr[k4];
        acc += xv.x * sW1[(k4 * 4 + 0) * HDIM + j];
        acc += xv.y * sW1[(k4 * 4 + 1) * HDIM + j];
        acc += xv.z * sW1[(k4 * 4 + 2) * HDIM + j];
        acc += xv.w * sW1[(k4 * 4 + 3) * HDIM + j];
    }
    g_h[idx] = acc * dinv;

    if (j == 0) {
        g_dinv[row] = dinv;
        g_deg[row]  = 0.0f;    // self-clean for next replay
    }
}

// ---- launches 3 & 5: pure gather/scatter aggregation (no norm, no self-loops) ----
template <int PASS>
__global__ void agg_kernel(const unsigned int* __restrict__ ei) {
    int e = blockIdx.x * blockDim.x + threadIdx.x;
    if (e >= E_EDGES) return;

    float* __restrict__ acc = (PASS == 0) ? g_acc1 : g_acc2;

    int mode = g_mode;
    int r = load_edge_idx(ei, mode, e);
    int c = load_edge_idx(ei, mode, E_EDGES + e);
    if (r < 0 || r >= N_NODES || c < 0 || c >= N_NODES) return;

    const float4* hr = (const float4*)(g_h + r * HDIM);
    float*        ac = acc + c * HDIM;
#pragma unroll
    for (int p = 0; p < HDIM / 4; p++)
        red_add_f4(ac + p * 4, hr[p]);
}

// ---- launch 4: z1s = dinv * relu(dinv*(acc1 + h1s) + b1); reset acc1 ----
__global__ void relu_bias_kernel(const float* __restrict__ b1) {
    int idx = blockIdx.x * blockDim.x + threadIdx.x;
    if (idx >= N_NODES * HDIM) return;
    int j    = idx & 15;
    int node = idx >> 4;
    float dinv = g_dinv[node];
    float z = fmaxf(dinv * (g_acc1[idx] + g_h[idx]) + b1[j], 0.0f);
    g_h[idx]    = dinv * z;    // z1s for layer 2
    g_acc1[idx] = 0.0f;        // self-clean
}

// ---- launch 6: out = log_softmax(dinv*(acc2 + z1s) @ W2 + b2); reset acc2 ----
__global__ void final_kernel(const float* __restrict__ W2, const float* __restrict__ b2,
                             float* __restrict__ out) {
    __shared__ float sW2[HDIM * FDIM];
    __shared__ float sb2[FDIM];
    for (int i = threadIdx.x; i < HDIM * FDIM; i += blockDim.x) sW2[i] = W2[i];
    for (int i = threadIdx.x; i < FDIM; i += blockDim.x)        sb2[i] = b2[i];
    __syncthreads();

    int warp = (blockIdx.x * blockDim.x + threadIdx.x) >> 5;
    int lane = threadIdx.x & 31;
    if (warp >= N_NODES) return;

    float dinv = g_dinv[warp];
    const float* ar = g_acc2 + warp * HDIM;
    const float* zr = g_h    + warp * HDIM;
    float a[HDIM];
#pragma unroll
    for (int k = 0; k < HDIM; k++)
        a[k] = dinv * (ar[k] + zr[k]);   // broadcast loads within warp

    // self-clean acc2 (lanes 0-3 each zero one float4)
    if (lane < 4)
        *(float4*)(g_acc2 + warp * HDIM + lane * 4) = make_float4(0.f, 0.f, 0.f, 0.f);

    int c0 = lane * 4;
    float o0 = sb2[c0 + 0], o1 = sb2[c0 + 1], o2 = sb2[c0 + 2], o3 = sb2[c0 + 3];
#pragma unroll
    for (int k = 0; k < HDIM; k++) {
        float4 w = *(const float4*)&sW2[k * FDIM + c0];
        o0 += a[k] * w.x; o1 += a[k] * w.y; o2 += a[k] * w.z; o3 += a[k] * w.w;
    }

    float m = fmaxf(fmaxf(o0, o1), fmaxf(o2, o3));
#pragma unroll
    for (int off = 16; off > 0; off >>= 1)
        m = fmaxf(m, __shfl_xor_sync(0xFFFFFFFFu, m, off));

    float s = expf(o0 - m) + expf(o1 - m) + expf(o2 - m) + expf(o3 - m);
#pragma unroll
    for (int off = 16; off > 0; off >>= 1)
        s += __shfl_xor_sync(0xFFFFFFFFu, s, off);
    float lse = m + logf(s);

    float4 r = make_float4(o0 - lse, o1 - lse, o2 - lse, o3 - lse);
    *(float4*)(out + (size_t)warp * FDIM + c0) = r;
}

extern "C" void kernel_launch(void* const* d_in, const int* in_sizes, int n_in,
                              void* d_out, int out_size) {
    const float*        x  = nullptr;
    const unsigned int* ei = nullptr;
    const float*        W1 = nullptr;
    const float*        W2 = nullptr;
    const float*        b1 = nullptr;
    const float*        b2 = nullptr;

    for (int i = 0; i < n_in; i++) {
        long long sz = in_sizes[i];
        if (sz == 6400000LL || sz == 25600000LL)        x  = (const float*)d_in[i];
        else if (sz == 1200000LL || sz == 2400000LL ||
                 sz == 4800000LL || sz == 9600000LL)     ei = (const unsigned int*)d_in[i];
        else if (sz == 2048LL || sz == 8192LL) { if (!W1) W1 = (const float*)d_in[i];
                                                 else     W2 = (const float*)d_in[i]; }
        else if (sz == 16LL  || sz == 64LL)              b1 = (const float*)d_in[i];
        else if (sz == 128LL || sz == 512LL)             b2 = (const float*)d_in[i];
    }
    if (!x)  x  = (const float*)d_in[0];
    if (!ei) ei = (const unsigned int*)d_in[1];
    if (!W1) W1 = (const float*)d_in[2];
    if (!b1) b1 = (const float*)d_in[3];
    if (!W2) W2 = (const float*)d_in[4];
    if (!b2) b2 = (const float*)d_in[5];

    float* out = (float*)d_out;
    const int T = 256;

    detect_kernel<<<1, T>>>(ei);                                    // 0
    deg_kernel<<<(E_EDGES + T - 1) / T, T>>>(ei);                   // 1
    gemm1_kernel<<<(N_NODES * HDIM + T - 1) / T, T>>>(x, W1);       // 2
    agg_kernel<0><<<(E_EDGES + T - 1) / T, T>>>(ei);                // 3
    relu_bias_kernel<<<(N_NODES * HDIM + T - 1) / T, T>>>(b1);      // 4
    agg_kernel<1><<<(E_EDGES + T - 1) / T, T>>>(ei);                // 5  <- ncu -s 5
    final_kernel<<<(N_NODES * 32 + T - 1) / T, T>>>(W2, b2, out);   // 6
}